// round 1
// baseline (speedup 1.0000x reference)
#include <cuda_runtime.h>

// Problem constants
#define B   2048
#define F   128    // nfield
#define E   128    // nemb
#define KH  8      // nhead
#define O   64     // nhid
#define Y   64     // d_k

// fold (alpha-1) * d_k^-0.5 = 0.5 * 0.125 = 0.0625 into C so GEMM outputs xs directly
#define FOLD 0.0625f

#define XCHUNK     16
#define XS_STRIDE  132   // padded row stride for transposed x chunk
#define ATT_STRIDE 132
#define NEWTON_ITERS 16

// Precomputed combined projection: C[k][x][o] = FOLD * sum_y W[k][x][y] * Q[k][o][y]
__device__ float g_C[KH * E * O];

// ---------------------------------------------------------------------------
// Kernel 1: tiny precompute of C (8 MFLOP total)
// grid = KH*E blocks, 64 threads (one per o)
// ---------------------------------------------------------------------------
__global__ void prep_kernel(const float* __restrict__ W, const float* __restrict__ Q) {
    int kx = blockIdx.x;          // k*E + x
    int k  = kx >> 7;             // /128
    int o  = threadIdx.x;         // 0..63

    __shared__ float wrow[Y];
    wrow[o] = W[kx * Y + o];      // W[k][x][y], y == threadIdx
    __syncthreads();

    const float* q = Q + (k * O + o) * Y;
    float acc = 0.0f;
#pragma unroll
    for (int y = 0; y < Y; y++)
        acc = fmaf(wrow[y], q[y], acc);

    g_C[kx * O + o] = acc * FOLD;
}

// ---------------------------------------------------------------------------
// Kernel 2: fused  xs-GEMM  ->  entmax-1.5 (Newton)  ->  * values
// one CTA per (b,k); 256 threads
// ---------------------------------------------------------------------------
__global__ __launch_bounds__(256)
void sparse_att_kernel(const float* __restrict__ Xg,
                       const float* __restrict__ Vg,
                       float* __restrict__ out) {
    // smem union:
    //   phase A: Cs[128*64] floats (0..8191)  +  XsT[16*132] floats (8192..10303)
    //   phase B: att[64*132] floats (0..8447)
    __shared__ __align__(16) float sm[E * O + XCHUNK * XS_STRIDE];  // 10304 floats = 41216 B
    float* Cs  = sm;                // [x][o], stride O
    float* XsT = sm + E * O;        // [xl][f], stride XS_STRIDE
    float* att = sm;                // [o][f], stride ATT_STRIDE (reused after GEMM)

    const int bid  = blockIdx.x;    // b*KH + k
    const int b    = bid >> 3;
    const int k    = bid & 7;
    const int tid  = threadIdx.x;
    const int warp = tid >> 5;
    const int lane = tid & 31;
    const int o_base = warp * 8;    // 8 warps x 8 rows = 64 o
    const int f_base = lane * 4;    // 32 lanes x 4 cols = 128 f

    // --- stage C[k] into smem (linear copy, [x][o]) ---
    const float* Ck = g_C + k * (E * O);
    for (int i = tid; i < E * O; i += 256)
        Cs[i] = Ck[i];

    // --- GEMM: att[o][f] = sum_x Cs[x][o] * X[b][f][x], x in 8 chunks of 16 ---
    float4 acc[8];
#pragma unroll
    for (int j = 0; j < 8; j++) acc[j] = make_float4(0.f, 0.f, 0.f, 0.f);

    const float4* Xb4 = reinterpret_cast<const float4*>(Xg + (long)b * F * E);

    for (int c = 0; c < 8; c++) {
        __syncthreads();   // Cs ready (c==0) / previous chunk consumed
        // load + transpose 128f x 16x chunk: XsT[xl][f] = X[b][f][c*16+xl]
        for (int i = tid; i < F * 4; i += 256) {     // 512 float4 loads
            int f  = i >> 2;
            int qq = i & 3;
            float4 t = Xb4[f * (E / 4) + c * 4 + qq];
            int xl = qq * 4;
            XsT[(xl + 0) * XS_STRIDE + f] = t.x;
            XsT[(xl + 1) * XS_STRIDE + f] = t.y;
            XsT[(xl + 2) * XS_STRIDE + f] = t.z;
            XsT[(xl + 3) * XS_STRIDE + f] = t.w;
        }
        __syncthreads();

        const int xg0 = c * XCHUNK;
#pragma unroll
        for (int j = 0; j < XCHUNK; j++) {
            float4 xx = *reinterpret_cast<const float4*>(&XsT[j * XS_STRIDE + f_base]);
            float4 ca = *reinterpret_cast<const float4*>(&Cs[(xg0 + j) * O + o_base]);
            float4 cb = *reinterpret_cast<const float4*>(&Cs[(xg0 + j) * O + o_base + 4]);
            const float cv[8] = {ca.x, ca.y, ca.z, ca.w, cb.x, cb.y, cb.z, cb.w};
#pragma unroll
            for (int oo = 0; oo < 8; oo++) {
                acc[oo].x = fmaf(cv[oo], xx.x, acc[oo].x);
                acc[oo].y = fmaf(cv[oo], xx.y, acc[oo].y);
                acc[oo].z = fmaf(cv[oo], xx.z, acc[oo].z);
                acc[oo].w = fmaf(cv[oo], xx.w, acc[oo].w);
            }
        }
    }

    __syncthreads();   // all GEMM reads of Cs/XsT done; safe to overwrite with att

    // --- spill att (= xs) to smem so each thread can own 32 contiguous f ---
#pragma unroll
    for (int oo = 0; oo < 8; oo++)
        *reinterpret_cast<float4*>(&att[(o_base + oo) * ATT_STRIDE + f_base]) = acc[oo];
    __syncthreads();

    // --- entmax-1.5 via Newton; 4 lanes per row, 32 elems each ---
    const int row = tid >> 2;   // 0..63  (= o)
    const int seg = tid & 3;    // quarter of the f dimension

    float z[32];
    {
        const float* arow = &att[row * ATT_STRIDE + seg * 32];
#pragma unroll
        for (int i = 0; i < 32; i += 4) {
            float4 t = *reinterpret_cast<const float4*>(&arow[i]);
            z[i] = t.x; z[i + 1] = t.y; z[i + 2] = t.z; z[i + 3] = t.w;
        }
    }

    float mx = z[0];
#pragma unroll
    for (int i = 1; i < 32; i++) mx = fmaxf(mx, z[i]);
    mx = fmaxf(mx, __shfl_xor_sync(0xffffffffu, mx, 1));
    mx = fmaxf(mx, __shfl_xor_sync(0xffffffffu, mx, 2));

    float tau = mx - 1.0f;   // g(tau0) >= 1, left of root; Newton is monotone from here

#pragma unroll 1
    for (int it = 0; it < NEWTON_ITERS; it++) {
        float g = 0.0f, s = 0.0f;
#pragma unroll
        for (int i = 0; i < 32; i++) {
            float r = fmaxf(z[i] - tau, 0.0f);
            g = fmaf(r, r, g);
            s += r;
        }
        g += __shfl_xor_sync(0xffffffffu, g, 1);
        g += __shfl_xor_sync(0xffffffffu, g, 2);
        s += __shfl_xor_sync(0xffffffffu, s, 1);
        s += __shfl_xor_sync(0xffffffffu, s, 2);
        // g' = -2s, s >= 1 along the iterate path -> safe, well-conditioned step
        tau += __fdividef(g - 1.0f, 2.0f * s);
    }

    // --- final p, normalization, multiply by values, store ---
    float psum = 0.0f;
#pragma unroll
    for (int i = 0; i < 32; i++) {
        float r = fmaxf(z[i] - tau, 0.0f);
        z[i] = r * r;
        psum += z[i];
    }
    psum += __shfl_xor_sync(0xffffffffu, psum, 1);
    psum += __shfl_xor_sync(0xffffffffu, psum, 2);
    float inv = __fdividef(1.0f, psum);

    const float* vrow = Vg + (k * O + row) * F + seg * 32;
    float* orow = out + (((long)(b * KH + k) * O + row) * F) + seg * 32;
#pragma unroll
    for (int i = 0; i < 32; i += 4) {
        float4 v = *reinterpret_cast<const float4*>(&vrow[i]);
        float4 p;
        p.x = z[i]     * inv * v.x;
        p.y = z[i + 1] * inv * v.y;
        p.z = z[i + 2] * inv * v.z;
        p.w = z[i + 3] * inv * v.w;
        *reinterpret_cast<float4*>(&orow[i]) = p;
    }
}

// ---------------------------------------------------------------------------
extern "C" void kernel_launch(void* const* d_in, const int* in_sizes, int n_in,
                              void* d_out, int out_size) {
    const float* x = (const float*)d_in[0];   // [2048,128,128]
    const float* w = (const float*)d_in[1];   // [8,128,64]
    const float* q = (const float*)d_in[2];   // [8,64,64]
    const float* v = (const float*)d_in[3];   // [8,64,128]
    float* out = (float*)d_out;               // [2048,8,64,128]

    prep_kernel<<<KH * E, 64>>>(w, q);
    sparse_att_kernel<<<B * KH, 256>>>(x, v, out);
}

// round 3
// speedup vs baseline: 1.4500x; 1.4500x over previous
#include <cuda_runtime.h>
#include <cuda_bf16.h>
#include <cstdint>

#define B_   2048
#define F_   128
#define E_   128
#define KH   8
#define O_   64
#define FOLD 0.0625f     // (alpha-1) * d_k^-0.5 folded into C
#define NIT  12          // Newton iterations

// ---------------- device scratch (static, allowed) ----------------
__device__ __align__(16) __nv_bfloat16 g_xhi[B_ * F_ * E_];
__device__ __align__(16) __nv_bfloat16 g_xlo[B_ * F_ * E_];
__device__ __align__(16) __nv_bfloat16 g_Ch[4 * 128 * 128];  // [hp][m][x]
__device__ __align__(16) __nv_bfloat16 g_Cl[4 * 128 * 128];

// smem: Xh tile [128][272B] + Xl tile [128][272B]
#define XSTRIDE 272
#define XLOFF   (128 * XSTRIDE)
#define SM_TOTAL (2 * 128 * XSTRIDE)   // 69632 B

__device__ __forceinline__ uint32_t smem_u32(const void* p) {
    uint32_t a;
    asm("{ .reg .u64 t; cvta.to.shared.u64 t, %1; cvt.u32.u64 %0, t; }" : "=r"(a) : "l"(p));
    return a;
}

__device__ __forceinline__ void mma_bf16(float* d,
                                         uint32_t a0, uint32_t a1, uint32_t a2, uint32_t a3,
                                         uint32_t b0, uint32_t b1) {
    asm volatile("mma.sync.aligned.m16n8k16.row.col.f32.bf16.bf16.f32 "
                 "{%0,%1,%2,%3}, {%4,%5,%6,%7}, {%8,%9}, {%0,%1,%2,%3};"
                 : "+f"(d[0]), "+f"(d[1]), "+f"(d[2]), "+f"(d[3])
                 : "r"(a0), "r"(a1), "r"(a2), "r"(a3), "r"(b0), "r"(b1));
}

__device__ __forceinline__ void ldmx4(uint32_t& b0, uint32_t& b1, uint32_t& b2, uint32_t& b3,
                                      uint32_t addr) {
    asm volatile("ldmatrix.sync.aligned.m8n8.x4.shared.b16 {%0,%1,%2,%3}, [%4];"
                 : "=r"(b0), "=r"(b1), "=r"(b2), "=r"(b3) : "r"(addr));
}

// ---------------------------------------------------------------------------
// prep: C[hp][m][x] = FOLD * sum_y W[k][x][y]*Q[k][o][y], bf16 hi/lo split
// grid = KH*E (1024), 64 threads (one per o)
// ---------------------------------------------------------------------------
__global__ void prep_kernel(const float* __restrict__ W, const float* __restrict__ Q) {
    int kx = blockIdx.x;          // k*128 + x
    int k  = kx >> 7;
    int x  = kx & 127;
    int o  = threadIdx.x;

    __shared__ float wrow[64];
    wrow[o] = W[kx * 64 + o];
    __syncthreads();

    const float* q = Q + (k * O_ + o) * 64;
    float acc = 0.0f;
#pragma unroll
    for (int y = 0; y < 64; y++) acc = fmaf(wrow[y], q[y], acc);
    acc *= FOLD;

    int hp = k >> 1;
    int m  = (k & 1) * 64 + o;
    __nv_bfloat16 h = __float2bfloat16(acc);
    g_Ch[(hp * 128 + m) * 128 + x] = h;
    g_Cl[(hp * 128 + m) * 128 + x] = __float2bfloat16(acc - __bfloat162float(h));
}

// ---------------------------------------------------------------------------
// split X into bf16 hi/lo
// ---------------------------------------------------------------------------
__global__ void split_x_kernel(const float* __restrict__ X) {
    size_t i = (size_t)blockIdx.x * blockDim.x + threadIdx.x;   // float4 index
    const float4* X4 = (const float4*)X;
    float4 v = X4[i];
    __nv_bfloat16 hx = __float2bfloat16(v.x), hy = __float2bfloat16(v.y);
    __nv_bfloat16 hz = __float2bfloat16(v.z), hw = __float2bfloat16(v.w);
    __nv_bfloat162* H = (__nv_bfloat162*)g_xhi;
    __nv_bfloat162* L = (__nv_bfloat162*)g_xlo;
    H[2 * i]     = __nv_bfloat162{hx, hy};
    H[2 * i + 1] = __nv_bfloat162{hz, hw};
    L[2 * i]     = __nv_bfloat162{__float2bfloat16(v.x - __bfloat162float(hx)),
                                  __float2bfloat16(v.y - __bfloat162float(hy))};
    L[2 * i + 1] = __nv_bfloat162{__float2bfloat16(v.z - __bfloat162float(hz)),
                                  __float2bfloat16(v.w - __bfloat162float(hw))};
}

// ---------------------------------------------------------------------------
// main: HMMA bf16 3-term GEMM + entmax-1.5 (Newton) + values
// one CTA per (b, head-pair); 256 threads (8 warps, warp = m16 x n128 strip)
// ---------------------------------------------------------------------------
__global__ __launch_bounds__(256, 2)
void main_kernel(const float* __restrict__ Vg, float* __restrict__ out) {
    extern __shared__ char smem[];
    const int tid  = threadIdx.x;
    const int wid  = tid >> 5;
    const int lane = tid & 31;
    const int b    = blockIdx.x >> 2;
    const int hp   = blockIdx.x & 3;
    const int mw   = wid * 16;

    // ---- stage X hi/lo tiles into smem (padded 272B rows) ----
    {
        const uint4* hb = (const uint4*)(g_xhi + (size_t)b * F_ * E_);
        const uint4* lb = (const uint4*)(g_xlo + (size_t)b * F_ * E_);
#pragma unroll
        for (int i = tid; i < 2048; i += 256) {
            int row = i >> 4, c = i & 15;
            *(uint4*)(smem + row * XSTRIDE + c * 16)         = hb[i];
            *(uint4*)(smem + XLOFF + row * XSTRIDE + c * 16) = lb[i];
        }
    }
    __syncthreads();

    // ---- MMA mainloop ----
    float acc[16][4];
#pragma unroll
    for (int t = 0; t < 16; t++)
#pragma unroll
        for (int j = 0; j < 4; j++) acc[t][j] = 0.0f;

    const int g  = lane >> 2;       // group id (row within m8)
    const int tg = lane & 3;        // thread in group
    // ldmatrix lane addressing: row = (lane&7) + ((lane>>4)<<3), chunk = (lane>>3)&1
    const int ln   = (lane & 7) + ((lane >> 4) << 3);
    const int lk8  = (lane >> 3) & 1;
    const uint32_t sbase = smem_u32(smem);

#pragma unroll
    for (int term = 0; term < 3; term++) {
        const uint16_t* A = (const uint16_t*)(((term == 2) ? g_Cl : g_Ch) + (hp * 128 + mw) * 128);
        const uint32_t xoff = (term == 1) ? (uint32_t)XLOFF : 0u;
#pragma unroll
        for (int kt = 0; kt < 8; kt++) {
            const int k0 = kt * 16 + 2 * tg;
            uint32_t a0 = *(const uint32_t*)(A + (g)     * 128 + k0);
            uint32_t a1 = *(const uint32_t*)(A + (g + 8) * 128 + k0);
            uint32_t a2 = *(const uint32_t*)(A + (g)     * 128 + k0 + 8);
            uint32_t a3 = *(const uint32_t*)(A + (g + 8) * 128 + k0 + 8);
            uint32_t raddr = sbase + xoff + (uint32_t)(ln * XSTRIDE + (kt * 2 + lk8) * 16);
#pragma unroll
            for (int nt2 = 0; nt2 < 8; nt2++) {
                uint32_t b0, b1, b2, b3;
                ldmx4(b0, b1, b2, b3, raddr + (uint32_t)(nt2 * 16 * XSTRIDE));
                mma_bf16(acc[2 * nt2],     a0, a1, a2, a3, b0, b1);
                mma_bf16(acc[2 * nt2 + 1], a0, a1, a2, a3, b2, b3);
            }
        }
    }

    // ---- epilogue: entmax-1.5, fully warp-local ----
    // lane holds rowA = mw + g (acc[t][0..1]) and rowB = rowA + 8 (acc[t][2..3]);
    // row is spread across the 4 lanes of a quad (32 vals each).
    float mA = acc[0][0], mB = acc[0][2];
#pragma unroll
    for (int t = 0; t < 16; t++) {
        mA = fmaxf(mA, fmaxf(acc[t][0], acc[t][1]));
        mB = fmaxf(mB, fmaxf(acc[t][2], acc[t][3]));
    }
    mA = fmaxf(mA, __shfl_xor_sync(0xffffffffu, mA, 1));
    mA = fmaxf(mA, __shfl_xor_sync(0xffffffffu, mA, 2));
    mB = fmaxf(mB, __shfl_xor_sync(0xffffffffu, mB, 1));
    mB = fmaxf(mB, __shfl_xor_sync(0xffffffffu, mB, 2));

    float tauA = mA - 1.0f, tauB = mB - 1.0f;

#pragma unroll 1
    for (int it = 0; it < NIT; it++) {
        float sA = 0.f, qA = 0.f, sB = 0.f, qB = 0.f;
#pragma unroll
        for (int t = 0; t < 16; t++) {
            float r0 = fmaxf(acc[t][0] - tauA, 0.f);
            float r1 = fmaxf(acc[t][1] - tauA, 0.f);
            float r2 = fmaxf(acc[t][2] - tauB, 0.f);
            float r3 = fmaxf(acc[t][3] - tauB, 0.f);
            qA = fmaf(r0, r0, qA); sA += r0;
            qA = fmaf(r1, r1, qA); sA += r1;
            qB = fmaf(r2, r2, qB); sB += r2;
            qB = fmaf(r3, r3, qB); sB += r3;
        }
        qA += __shfl_xor_sync(0xffffffffu, qA, 1);
        qA += __shfl_xor_sync(0xffffffffu, qA, 2);
        sA += __shfl_xor_sync(0xffffffffu, sA, 1);
        sA += __shfl_xor_sync(0xffffffffu, sA, 2);
        qB += __shfl_xor_sync(0xffffffffu, qB, 1);
        qB += __shfl_xor_sync(0xffffffffu, qB, 2);
        sB += __shfl_xor_sync(0xffffffffu, sB, 1);
        sB += __shfl_xor_sync(0xffffffffu, sB, 2);
        tauA += __fdividef(qA - 1.0f, 2.0f * sA);
        tauB += __fdividef(qB - 1.0f, 2.0f * sB);
    }

    // final p = r^2, row sums, normalize, * values, store
    float pA = 0.f, pB = 0.f;
#pragma unroll
    for (int t = 0; t < 16; t++) {
        float r0 = fmaxf(acc[t][0] - tauA, 0.f);
        float r1 = fmaxf(acc[t][1] - tauA, 0.f);
        float r2 = fmaxf(acc[t][2] - tauB, 0.f);
        float r3 = fmaxf(acc[t][3] - tauB, 0.f);
        acc[t][0] = r0 * r0; pA += acc[t][0];
        acc[t][1] = r1 * r1; pA += acc[t][1];
        acc[t][2] = r2 * r2; pB += acc[t][2];
        acc[t][3] = r3 * r3; pB += acc[t][3];
    }
    pA += __shfl_xor_sync(0xffffffffu, pA, 1);
    pA += __shfl_xor_sync(0xffffffffu, pA, 2);
    pB += __shfl_xor_sync(0xffffffffu, pB, 1);
    pB += __shfl_xor_sync(0xffffffffu, pB, 2);
    const float invA = __fdividef(1.0f, pA);
    const float invB = __fdividef(1.0f, pB);

    const int rowA = mw + g;            // 0..127
    const int rowB = rowA + 8;
    const int k  = hp * 2 + (rowA >> 6);
    const int oA = rowA & 63;
    const int oB = rowB & 63;
    const float* vA = Vg + (k * O_ + oA) * F_;
    const float* vB = Vg + (k * O_ + oB) * F_;
    float* outA = out + (((size_t)b * KH + k) * O_ + oA) * F_;
    float* outB = out + (((size_t)b * KH + k) * O_ + oB) * F_;

#pragma unroll
    for (int t = 0; t < 16; t++) {
        int col = t * 8 + 2 * tg;
        float2 va = *(const float2*)(vA + col);
        float2 vb = *(const float2*)(vB + col);
        float2 wa, wb;
        wa.x = acc[t][0] * invA * va.x;
        wa.y = acc[t][1] * invA * va.y;
        wb.x = acc[t][2] * invB * vb.x;
        wb.y = acc[t][3] * invB * vb.y;
        *(float2*)(outA + col) = wa;
        *(float2*)(outB + col) = wb;
    }
}

// ---------------------------------------------------------------------------
extern "C" void kernel_launch(void* const* d_in, const int* in_sizes, int n_in,
                              void* d_out, int out_size) {
    const float* x = (const float*)d_in[0];   // [2048,128,128]
    const float* w = (const float*)d_in[1];   // [8,128,64]
    const float* q = (const float*)d_in[2];   // [8,64,64]
    const float* v = (const float*)d_in[3];   // [8,64,128]
    float* out = (float*)d_out;               // [2048,8,64,128]

    cudaFuncSetAttribute(main_kernel, cudaFuncAttributeMaxDynamicSharedMemorySize, SM_TOTAL);

    prep_kernel<<<KH * E_, 64>>>(w, q);
    split_x_kernel<<<(B_ * F_ * E_ / 4) / 256, 256>>>(x);
    main_kernel<<<B_ * 4, 256, SM_TOTAL>>>(v, out);
}